// round 1
// baseline (speedup 1.0000x reference)
#include <cuda_runtime.h>

// Problem dims (fixed by the dataset)
#define Bv 64
#define Hv 128
#define Wv 128
#define Cv 3
#define Nv 10
#define KHW 5
#define PADv 2

#define TH 16                    // output rows per block
#define TILE_ROWS (TH + 4)       // 20 (with halo)
#define TILE_COLS (Wv + 4)       // 132 (with halo)
#define NTHREADS 512

// out[n][b][c][h][w] = sum_{kh,kw} images[b][h+kh-2][w+kw-2][c] * kernels[b][kh][kw][n]
__global__ __launch_bounds__(NTHREADS, 2)
void cdna_apply_kernel(const float* __restrict__ images,
                       const float* __restrict__ kernels,
                       float* __restrict__ out)
{
    __shared__ float tile[TILE_ROWS][TILE_COLS];
    __shared__ float ksm[25][12];   // 12-float stride -> 16B-aligned float4 reads

    const int tx  = threadIdx.x;            // 0..127  (w)
    const int ty  = threadIdx.y;            // 0..3
    const int tid = ty * 128 + tx;
    const int rt  = blockIdx.x;              // row tile 0..7
    const int c   = blockIdx.y;              // 0..2
    const int b   = blockIdx.z;              // 0..63
    const int r0  = rt * TH;

    // ---- stage kernel weights: kernels[(b*25 + tap)*10 + n] ----
    if (tid < 250) {
        int tap = tid / Nv;
        int n   = tid - tap * Nv;
        ksm[tap][n] = kernels[(b * 25 + tap) * Nv + n];
    }

    // ---- stage image tile with zero-padded halo ----
    const float* imgb = images + ((size_t)b * Hv) * (Wv * Cv) + c;
    #pragma unroll
    for (int i = tid; i < TILE_ROWS * TILE_COLS; i += NTHREADS) {
        int r  = i / TILE_COLS;
        int cc = i - r * TILE_COLS;
        int gh = r0 + r - PADv;
        int gw = cc - PADv;
        float v = 0.0f;
        if (gh >= 0 && gh < Hv && gw >= 0 && gw < Wv)
            v = imgb[(gh * Wv + gw) * Cv];
        tile[r][cc] = v;
    }
    __syncthreads();

    // ---- compute: each thread does 4 rows x 1 col x 10 kernels ----
    float acc[4][Nv];
    #pragma unroll
    for (int rr = 0; rr < 4; rr++)
        #pragma unroll
        for (int n = 0; n < Nv; n++)
            acc[rr][n] = 0.0f;

    const int br = ty * 4;  // local base row in output space

    #pragma unroll
    for (int kh = 0; kh < KHW; kh++) {
        #pragma unroll
        for (int kw = 0; kw < KHW; kw++) {
            const int tap = kh * KHW + kw;
            const float4 k0 = *reinterpret_cast<const float4*>(&ksm[tap][0]);
            const float4 k1 = *reinterpret_cast<const float4*>(&ksm[tap][4]);
            const float2 k2 = *reinterpret_cast<const float2*>(&ksm[tap][8]);
            #pragma unroll
            for (int rr = 0; rr < 4; rr++) {
                const float v = tile[br + rr + kh][tx + kw];
                acc[rr][0] += v * k0.x;
                acc[rr][1] += v * k0.y;
                acc[rr][2] += v * k0.z;
                acc[rr][3] += v * k0.w;
                acc[rr][4] += v * k1.x;
                acc[rr][5] += v * k1.y;
                acc[rr][6] += v * k1.z;
                acc[rr][7] += v * k1.w;
                acc[rr][8] += v * k2.x;
                acc[rr][9] += v * k2.y;
            }
        }
    }

    // ---- store: out[(((n*B + b)*C + c)*H + h)*W + w], coalesced in w ----
    #pragma unroll
    for (int rr = 0; rr < 4; rr++) {
        const int h = r0 + br + rr;
        #pragma unroll
        for (int n = 0; n < Nv; n++) {
            size_t idx = ((((size_t)n * Bv + b) * Cv + c) * Hv + h) * Wv + tx;
            out[idx] = acc[rr][n];
        }
    }
}

extern "C" void kernel_launch(void* const* d_in, const int* in_sizes, int n_in,
                              void* d_out, int out_size)
{
    const float* images  = (const float*)d_in[0];   // [B,H,W,C]
    const float* kernels = (const float*)d_in[1];   // [B,KH,KW,N]
    float* out = (float*)d_out;                     // [N,B,C,H,W]

    dim3 block(128, 4, 1);
    dim3 grid(Hv / TH, Cv, Bv);   // (8, 3, 64)
    cdna_apply_kernel<<<grid, block>>>(images, kernels, out);
}

// round 2
// speedup vs baseline: 1.2826x; 1.2826x over previous
#include <cuda_runtime.h>

// Problem dims (fixed)
#define Bv 64
#define Hv 128
#define Wv 128
#define Cv 3
#define Nv 10

#define ROWS_PER_BLK 8
#define TILE_ROWS (ROWS_PER_BLK + 4)   // 12
#define TILE_COLS (Wv + 4)             // 132 floats (528B, 16B-multiple stride)
#define NTHREADS 256

// Packed dual-fp32 FMA (Blackwell FFMA2): d = a*b + d elementwise on float2.
__device__ __forceinline__ void ffma2(float2& d, const float2& a, const float2& b) {
    unsigned long long& dd = reinterpret_cast<unsigned long long&>(d);
    const unsigned long long aa = *reinterpret_cast<const unsigned long long*>(&a);
    const unsigned long long bb = *reinterpret_cast<const unsigned long long*>(&b);
    asm("fma.rn.f32x2 %0, %1, %2, %0;" : "+l"(dd) : "l"(aa), "l"(bb));
}

// out[n][b][c][h][w] = sum_{kh,kw} images[b][h+kh-2][w+kw-2][c] * kernels[b][kh][kw][n]
__global__ __launch_bounds__(NTHREADS)
void cdna_apply_kernel(const float* __restrict__ images,
                       const float* __restrict__ kernels,
                       float* __restrict__ out)
{
    __shared__ __align__(16) float tile[TILE_ROWS][TILE_COLS];
    __shared__ __align__(16) float ksm[25][12];   // [tap][n], 12-stride for float4 reads

    const int tid  = threadIdx.x;
    const int lane = tid & 31;          // w-group: 4 consecutive columns
    const int ty   = tid >> 5;          // 0..7: output row within block
    const int cx   = lane * 4;          // base output column (16B aligned)

    const int rt = blockIdx.x;          // row tile 0..15
    const int c  = blockIdx.y;          // 0..2
    const int b  = blockIdx.z;          // 0..63
    const int r0 = rt * ROWS_PER_BLK;

    // ---- stage kernel weights (n-contiguous => float2 pairs are natural) ----
    if (tid < 250) {
        int tap = tid / Nv;
        int n   = tid - tap * Nv;
        ksm[tap][n] = kernels[(b * 25 + tap) * Nv + n];
    }

    // ---- stage image tile with zero-padded halo ----
    const float* imgb = images + ((size_t)b * Hv) * (Wv * Cv) + c;
    for (int i = tid; i < TILE_ROWS * TILE_COLS; i += NTHREADS) {
        int r  = i / TILE_COLS;
        int cc = i - r * TILE_COLS;
        int gh = r0 + r - 2;
        int gw = cc - 2;
        float v = 0.0f;
        if (gh >= 0 && gh < Hv && gw >= 0 && gw < Wv)
            v = imgb[(gh * Wv + gw) * Cv];
        tile[r][cc] = v;
    }
    __syncthreads();

    // ---- compute: 1 row x 4 cols x 10 n per thread, n paired in f32x2 ----
    float2 acc[4][5];
    #pragma unroll
    for (int j = 0; j < 4; j++)
        #pragma unroll
        for (int p = 0; p < 5; p++)
            acc[j][p] = make_float2(0.0f, 0.0f);

    #pragma unroll
    for (int kh = 0; kh < 5; kh++) {
        // 8-wide input window for this kh row: two aligned LDS.128
        const float4 a0 = *reinterpret_cast<const float4*>(&tile[ty + kh][cx]);
        const float4 a1 = *reinterpret_cast<const float4*>(&tile[ty + kh][cx + 4]);
        float2 vv[8];
        vv[0] = make_float2(a0.x, a0.x);
        vv[1] = make_float2(a0.y, a0.y);
        vv[2] = make_float2(a0.z, a0.z);
        vv[3] = make_float2(a0.w, a0.w);
        vv[4] = make_float2(a1.x, a1.x);
        vv[5] = make_float2(a1.y, a1.y);
        vv[6] = make_float2(a1.z, a1.z);
        vv[7] = make_float2(a1.w, a1.w);

        #pragma unroll
        for (int kw = 0; kw < 5; kw++) {
            const int tap = kh * 5 + kw;
            const float4 w01 = *reinterpret_cast<const float4*>(&ksm[tap][0]);
            const float4 w23 = *reinterpret_cast<const float4*>(&ksm[tap][4]);
            const float2 w4  = *reinterpret_cast<const float2*>(&ksm[tap][8]);
            const float2 k0 = make_float2(w01.x, w01.y);
            const float2 k1 = make_float2(w01.z, w01.w);
            const float2 k2 = make_float2(w23.x, w23.y);
            const float2 k3 = make_float2(w23.z, w23.w);
            const float2 k4 = w4;
            #pragma unroll
            for (int j = 0; j < 4; j++) {
                const float2 v = vv[j + kw];
                ffma2(acc[j][0], v, k0);
                ffma2(acc[j][1], v, k1);
                ffma2(acc[j][2], v, k2);
                ffma2(acc[j][3], v, k3);
                ffma2(acc[j][4], v, k4);
            }
        }
    }

    // ---- store: out[(((n*B + b)*C + c)*H + h)*W + w], float4 per n ----
    const int h = r0 + ty;
    #pragma unroll
    for (int p = 0; p < 5; p++) {
        float4 e, o;
        e.x = acc[0][p].x; e.y = acc[1][p].x; e.z = acc[2][p].x; e.w = acc[3][p].x;
        o.x = acc[0][p].y; o.y = acc[1][p].y; o.z = acc[2][p].y; o.w = acc[3][p].y;
        const int ne = 2 * p;
        const int no = 2 * p + 1;
        size_t ie = ((((size_t)ne * Bv + b) * Cv + c) * Hv + h) * Wv + cx;
        size_t io = ((((size_t)no * Bv + b) * Cv + c) * Hv + h) * Wv + cx;
        *reinterpret_cast<float4*>(&out[ie]) = e;
        *reinterpret_cast<float4*>(&out[io]) = o;
    }
}

extern "C" void kernel_launch(void* const* d_in, const int* in_sizes, int n_in,
                              void* d_out, int out_size)
{
    const float* images  = (const float*)d_in[0];   // [B,H,W,C]
    const float* kernels = (const float*)d_in[1];   // [B,KH,KW,N]
    float* out = (float*)d_out;                     // [N,B,C,H,W]

    dim3 block(NTHREADS, 1, 1);
    dim3 grid(Hv / ROWS_PER_BLK, Cv, Bv);   // (16, 3, 64)
    cdna_apply_kernel<<<grid, block>>>(images, kernels, out);
}

// round 3
// speedup vs baseline: 1.9065x; 1.4864x over previous
#include <cuda_runtime.h>

// Problem dims (fixed)
#define Bv 64
#define Hv 128
#define Wv 128
#define Cv 3
#define Nv 10

#define ROWS_PER_BLK 8
#define TILE_ROWS (ROWS_PER_BLK + 4)   // 12
#define TILE_COLS (Wv + 4)             // 132 floats
#define NTHREADS 256

// Packed dual-fp32 FMA (Blackwell FFMA2): d = a*b + d elementwise on float2.
__device__ __forceinline__ void ffma2(float2& d, const float2& a, const float2& b) {
    unsigned long long& dd = reinterpret_cast<unsigned long long&>(d);
    const unsigned long long aa = *reinterpret_cast<const unsigned long long*>(&a);
    const unsigned long long bb = *reinterpret_cast<const unsigned long long*>(&b);
    asm("fma.rn.f32x2 %0, %1, %2, %0;" : "+l"(dd) : "l"(aa), "l"(bb));
}

// out[n][b][c][h][w] = sum_{kh,kw} images[b][h+kh-2][w+kw-2][c] * kernels[b][kh][kw][n]
__global__ __launch_bounds__(NTHREADS, 4)   // cap regs at 64 -> 4 blocks/SM
void cdna_apply_kernel(const float* __restrict__ images,
                       const float* __restrict__ kernels,
                       float* __restrict__ out)
{
    __shared__ __align__(16) float tile[TILE_ROWS][TILE_COLS];
    __shared__ __align__(16) float ksm[25][12];   // [tap][n], stride 12 for aligned float4

    const int tid  = threadIdx.x;
    const int lane = tid & 31;          // w-group: 4 consecutive columns
    const int ty   = tid >> 5;          // 0..7: output row within block
    const int cx   = lane * 4;          // base output column (16B aligned)

    const int rt = blockIdx.x;          // row tile 0..15
    const int c  = blockIdx.y;          // 0..2
    const int b  = blockIdx.z;          // 0..63
    const int r0 = rt * ROWS_PER_BLK;

    // ---- stage kernel weights ----
    if (tid < 250) {
        int tap = tid / Nv;
        int n   = tid - tap * Nv;
        ksm[tap][n] = kernels[(b * 25 + tap) * Nv + n];
    }

    // ---- stage image tile with zero-padded halo ----
    const float* imgb = images + ((size_t)b * Hv) * (Wv * Cv) + c;
    #pragma unroll
    for (int it = 0; it < 7; it++) {
        int i = it * NTHREADS + tid;
        if (i < TILE_ROWS * TILE_COLS) {
            int r  = i / TILE_COLS;
            int cc = i - r * TILE_COLS;
            int gh = r0 + r - 2;
            int gw = cc - 2;
            float v = 0.0f;
            if (gh >= 0 && gh < Hv && gw >= 0 && gw < Wv)
                v = imgb[(gh * Wv + gw) * Cv];
            tile[r][cc] = v;
        }
    }
    __syncthreads();

    // ---- compute: 1 row x 4 cols x 10 n per thread, n paired in f32x2 ----
    float2 acc[4][5];
    #pragma unroll
    for (int j = 0; j < 4; j++)
        #pragma unroll
        for (int p = 0; p < 5; p++)
            acc[j][p] = make_float2(0.0f, 0.0f);

    #pragma unroll
    for (int kh = 0; kh < 5; kh++) {
        // 8-wide input window for this kh row: two aligned LDS.128
        const float4 a0 = *reinterpret_cast<const float4*>(&tile[ty + kh][cx]);
        const float4 a1 = *reinterpret_cast<const float4*>(&tile[ty + kh][cx + 4]);
        float2 vv[8];
        vv[0] = make_float2(a0.x, a0.x);
        vv[1] = make_float2(a0.y, a0.y);
        vv[2] = make_float2(a0.z, a0.z);
        vv[3] = make_float2(a0.w, a0.w);
        vv[4] = make_float2(a1.x, a1.x);
        vv[5] = make_float2(a1.y, a1.y);
        vv[6] = make_float2(a1.z, a1.z);
        vv[7] = make_float2(a1.w, a1.w);

        #pragma unroll
        for (int kw = 0; kw < 5; kw++) {
            const int tap = kh * 5 + kw;
            const float4 w01 = *reinterpret_cast<const float4*>(&ksm[tap][0]);
            const float4 w23 = *reinterpret_cast<const float4*>(&ksm[tap][4]);
            const float2 w4  = *reinterpret_cast<const float2*>(&ksm[tap][8]);
            const float2 k0 = make_float2(w01.x, w01.y);
            const float2 k1 = make_float2(w01.z, w01.w);
            const float2 k2 = make_float2(w23.x, w23.y);
            const float2 k3 = make_float2(w23.z, w23.w);
            const float2 k4 = w4;
            #pragma unroll
            for (int j = 0; j < 4; j++) {
                const float2 v = vv[j + kw];
                ffma2(acc[j][0], v, k0);
                ffma2(acc[j][1], v, k1);
                ffma2(acc[j][2], v, k2);
                ffma2(acc[j][3], v, k3);
                ffma2(acc[j][4], v, k4);
            }
        }
    }

    // ---- store: out[(((n*B + b)*C + c)*H + h)*W + w], float4 per n ----
    const int h = r0 + ty;
    float* obase = out + (((size_t)b * Cv + c) * Hv + h) * Wv + cx;
    const size_t nstride = (size_t)Bv * Cv * Hv * Wv;
    #pragma unroll
    for (int p = 0; p < 5; p++) {
        float4 e, o;
        e.x = acc[0][p].x; e.y = acc[1][p].x; e.z = acc[2][p].x; e.w = acc[3][p].x;
        o.x = acc[0][p].y; o.y = acc[1][p].y; o.z = acc[2][p].y; o.w = acc[3][p].y;
        *reinterpret_cast<float4*>(obase + (size_t)(2 * p)     * nstride) = e;
        *reinterpret_cast<float4*>(obase + (size_t)(2 * p + 1) * nstride) = o;
    }
}

extern "C" void kernel_launch(void* const* d_in, const int* in_sizes, int n_in,
                              void* d_out, int out_size)
{
    const float* images  = (const float*)d_in[0];   // [B,H,W,C]
    const float* kernels = (const float*)d_in[1];   // [B,KH,KW,N]
    float* out = (float*)d_out;                     // [N,B,C,H,W]

    dim3 block(NTHREADS, 1, 1);
    dim3 grid(Hv / ROWS_PER_BLK, Cv, Bv);   // (16, 3, 64)
    cdna_apply_kernel<<<grid, block>>>(images, kernels, out);
}